// round 6
// baseline (speedup 1.0000x reference)
#include <cuda_runtime.h>
#include <cuda_bf16.h>
#include <cstdint>
#include <math.h>

// ---------------- problem constants ----------------
#define BATCH 16
#define EDIM  256
#define HWSZ  4096
#define NPIX  65536
#define RNUM  365
#define EK    768            // B split-K: [hi|hi|lo]
#define AK    512            // A split storage: [hi|lo] (chunks 8-11 re-read hi)
#define NT_R  32
#define NCOLS 96             // 3 modes * 32 r
#define NTILES 12
#define MPX   128

#define TOT1     ((size_t)BATCH * RNUM * HWSZ)
#define OFF_CLS    ((size_t)0)
#define OFF_CLSNEG (TOT1)
#define OFF_DIST   (2*TOT1)
#define OFF_DNEG   (3*TOT1)
#define OFF_PORI   (5*TOT1)

// ---------------- static device scratch ----------------
__device__ float g_xt[(size_t)NPIX * EDIM];                 // 64 MB  x transposed [px][c]
__device__ __nv_bfloat16 g_embA[(size_t)NPIX * AK];         // 64 MB  emb split [hi|lo]
__device__ __nv_bfloat16 g_B[(size_t)NTILES * NCOLS * EK];  // 1.7 MB
__device__ float g_part[NTILES][NPIX];
__device__ float g_sum[NPIX];

// ---------------- helpers ----------------
__device__ __forceinline__ uint32_t pk_bf2(__nv_bfloat16 a, __nv_bfloat16 b) {
    unsigned short ua = __bfloat16_as_ushort(a), ub = __bfloat16_as_ushort(b);
    return (uint32_t)ua | ((uint32_t)ub << 16);
}
__device__ __forceinline__ uint32_t smem_u32(const void* p) {
    uint32_t a;
    asm("{ .reg .u64 t; cvta.to.shared.u64 t, %1; cvt.u32.u64 %0, t; }" : "=r"(a) : "l"(p));
    return a;
}
__device__ __forceinline__ uint2 cvt_f4(float4 v, bool lo) {
    __nv_bfloat16 h0 = __float2bfloat16(v.x), h1 = __float2bfloat16(v.y),
                  h2 = __float2bfloat16(v.z), h3 = __float2bfloat16(v.w);
    if (lo) {
        h0 = __float2bfloat16(v.x - __bfloat162float(h0));
        h1 = __float2bfloat16(v.y - __bfloat162float(h1));
        h2 = __float2bfloat16(v.z - __bfloat162float(h2));
        h3 = __float2bfloat16(v.w - __bfloat162float(h3));
    }
    uint2 r; r.x = pk_bf2(h0, h1); r.y = pk_bf2(h2, h3); return r;
}

#define LDSM_X4(r0, r1, r2, r3, addr)                                          \
    asm volatile("ldmatrix.sync.aligned.m8n8.x4.shared.b16 {%0,%1,%2,%3}, [%4];" \
        : "=r"(r0), "=r"(r1), "=r"(r2), "=r"(r3) : "r"(addr))

#define MMA_BF16(c, a, b0, b1)                                                 \
    asm volatile("mma.sync.aligned.m16n8k16.row.col.f32.bf16.bf16.f32 "        \
        "{%0,%1,%2,%3}, {%4,%5,%6,%7}, {%8,%9}, {%0,%1,%2,%3};"                \
        : "+f"((c)[0]), "+f"((c)[1]), "+f"((c)[2]), "+f"((c)[3])               \
        : "r"((a)[0]), "r"((a)[1]), "r"((a)[2]), "r"((a)[3]), "r"(b0), "r"(b1))

// =====================================================================
// Kernel 0: transpose x[b][c][hw] -> g_xt[b*4096+hw][c]
// =====================================================================
__global__ __launch_bounds__(256) void transpose_kernel(const float* __restrict__ x)
{
    __shared__ float tl[32][33];
    const int hw0 = blockIdx.x * 32, c0 = blockIdx.y * 32, b = blockIdx.z;
    const int tx = threadIdx.x & 31, ty = threadIdx.x >> 5;
    const float* src = x + ((size_t)b * 256 + c0) * 4096 + hw0;
    #pragma unroll
    for (int j = 0; j < 4; j++)
        tl[ty * 4 + j][tx] = src[(size_t)(ty * 4 + j) * 4096 + tx];
    __syncthreads();
    float* dst = g_xt + ((size_t)b * 4096 + hw0) * 256 + c0;
    #pragma unroll
    for (int j = 0; j < 4; j++)
        dst[(size_t)(ty * 4 + j) * 256 + tx] = tl[tx][ty * 4 + j];
}

// =====================================================================
// Kernel 1: build B' (pos / neg0 / neg1, normalized, split bf16).
// =====================================================================
__global__ __launch_bounds__(256) void prep_reps_kernel(
    const float* __restrict__ reps,
    const float* __restrict__ negw,
    const float* __restrict__ negb)
{
    __shared__ float s_rep[8][256];
    __shared__ float s_off[8][512];
    const int tid = threadIdx.x;
    const int r0 = blockIdx.x * 8;
    const int w = tid >> 5, lane = tid & 31;

    #pragma unroll
    for (int i = 0; i < 8; i++) {
        int r = r0 + i;
        s_rep[i][tid] = (r < RNUM) ? reps[r * 256 + tid] : 0.f;
    }
    __syncthreads();

    for (int jj = 0; jj < 64; jj++) {
        int j = w * 64 + jj;
        float part[8];
        #pragma unroll
        for (int rl = 0; rl < 8; rl++) part[rl] = 0.f;
        #pragma unroll
        for (int i2 = 0; i2 < 8; i2++) {
            int k = lane + 32 * i2;
            float wv = negw[j * 256 + k];
            #pragma unroll
            for (int rl = 0; rl < 8; rl++) part[rl] += wv * fabsf(s_rep[rl][k]);
        }
        #pragma unroll
        for (int off = 16; off > 0; off >>= 1) {
            #pragma unroll
            for (int rl = 0; rl < 8; rl++)
                part[rl] += __shfl_xor_sync(0xffffffffu, part[rl], off);
        }
        if (lane < 8) s_off[lane][j] = part[lane] + negb[j];
    }
    __syncthreads();

    #pragma unroll
    for (int pi = 0; pi < 2; pi++) {
        int pair = w + pi * 8;
        int i = pair & 7, m = pair >> 3;
        float vals[8];
        float ss = 0.f;
        #pragma unroll
        for (int q = 0; q < 8; q++) {
            int e = lane + 32 * q;
            float rv = s_rep[i][e];
            float sg = (rv > 0.f ? 1.f : 0.f) - (rv < 0.f ? 1.f : 0.f);
            float v = (s_off[i][m * 256 + e] + fabsf(rv)) * sg;
            vals[q] = v;
            ss += v * v;
        }
        #pragma unroll
        for (int off = 16; off > 0; off >>= 1) ss += __shfl_xor_sync(0xffffffffu, ss, off);
        float inv = 1.f / fmaxf(sqrtf(ss), 1e-12f);
        int r = r0 + i;
        int t = r >> 5, rl = r & 31;
        size_t rowb = ((size_t)(t * NCOLS + (1 + m) * 32 + rl)) * EK;
        #pragma unroll
        for (int q = 0; q < 8; q++) {
            int e = lane + 32 * q;
            float f = vals[q] * inv;
            __nv_bfloat16 hb = __float2bfloat16(f);
            float lof = f - __bfloat162float(hb);
            g_B[rowb + e]       = hb;
            g_B[rowb + 256 + e] = hb;
            g_B[rowb + 512 + e] = __float2bfloat16(lof);
        }
    }
    #pragma unroll
    for (int i = 0; i < 8; i++) {
        int r = r0 + i;
        int t = r >> 5, rl = r & 31;
        float f = s_rep[i][tid];
        __nv_bfloat16 hb = __float2bfloat16(f);
        float lof = f - __bfloat162float(hb);
        size_t rowb = ((size_t)(t * NCOLS + rl)) * EK + tid;
        g_B[rowb]       = hb;
        g_B[rowb + 256] = hb;
        g_B[rowb + 512] = __float2bfloat16(lof);
    }
}

// =====================================================================
// Kernel 2: conv via mma.sync split-bf16. C[px(128)][e(256)], K=768.
// 512 threads, 16 warps (4m x 4n). Single-buffered smem.
// Epilogue: bias + L2 norm over e, write split [hi|lo] to g_embA.
// =====================================================================
#define CV_SA 0
#define CV_SB 16384
#define CV_CST 257
#define CV_CF_BYTES (128 * CV_CST * 4)     // 131584
#define CV_PSUM (131584)
#define CV_SBIAS (131584 + 2048)
#define CV_SMEM (131584 + 2048 + 1024)     // 134656

__global__ __launch_bounds__(512) void conv_mma_kernel(
    const float* __restrict__ W,
    const float* __restrict__ bias)
{
    extern __shared__ char smem[];
    const uint32_t sbase = smem_u32(smem);
    const int tid = threadIdx.x;
    const int lane = tid & 31;
    const int wid = tid >> 5;
    const int warp_m = wid & 3;
    const int warp_n = wid >> 2;
    const int p0 = blockIdx.x * MPX;

    if (tid < 256) ((float*)(smem + CV_SBIAS))[tid] = bias[tid];

    float acc[2][8][4];
    #pragma unroll
    for (int mt = 0; mt < 2; mt++)
        #pragma unroll
        for (int j = 0; j < 8; j++)
            #pragma unroll
            for (int q = 0; q < 4; q++) acc[mt][j][q] = 0.f;

    for (int s = 0; s < 12; s++) {
        const int c0 = (s & 3) << 6;
        const bool aLo = (s >= 4) && (s < 8);
        const bool bLo = (s >= 8);
        __syncthreads();
        // A: xt rows p0..p0+127, cols c0..c0+63 (fp32 -> bf16 hi/lo)
        #pragma unroll
        for (int i = 0; i < 4; i++) {
            int idx = tid + 512 * i;
            int row = idx >> 4, c4 = idx & 15;
            float4 v = *(const float4*)&g_xt[(size_t)(p0 + row) * 256 + c0 + c4 * 4];
            uint2 u = cvt_f4(v, aLo);
            int g = c4 >> 1, half = c4 & 1;
            *(uint2*)(smem + CV_SA + (row << 7) + (((g ^ (row & 7))) << 4) + (half << 3)) = u;
        }
        // B: W rows e 0..255, cols c0..c0+63
        #pragma unroll
        for (int i = 0; i < 8; i++) {
            int idx = tid + 512 * i;
            int row = idx >> 4, c4 = idx & 15;
            float4 v = *(const float4*)&W[(size_t)row * 256 + c0 + c4 * 4];
            uint2 u = cvt_f4(v, bLo);
            int g = c4 >> 1, half = c4 & 1;
            *(uint2*)(smem + CV_SB + (row << 7) + (((g ^ (row & 7))) << 4) + (half << 3)) = u;
        }
        __syncthreads();

        const uint32_t saA = sbase + CV_SA;
        const uint32_t saB = sbase + CV_SB;
        #pragma unroll
        for (int kk = 0; kk < 4; kk++) {
            uint32_t af[2][4];
            #pragma unroll
            for (int mt = 0; mt < 2; mt++) {
                int row = warp_m * 32 + mt * 16 + (lane & 15);
                int c = kk * 2 + (lane >> 4);
                uint32_t addr = saA + (((row << 3) + (c ^ (row & 7))) << 4);
                LDSM_X4(af[mt][0], af[mt][1], af[mt][2], af[mt][3], addr);
            }
            uint32_t bf[4][4];
            #pragma unroll
            for (int bp = 0; bp < 4; bp++) {
                int row = warp_n * 64 + bp * 16 + ((lane >> 4) << 3) + (lane & 7);
                int c = kk * 2 + ((lane >> 3) & 1);
                uint32_t addr = saB + (((row << 3) + (c ^ (row & 7))) << 4);
                LDSM_X4(bf[bp][0], bf[bp][1], bf[bp][2], bf[bp][3], addr);
            }
            #pragma unroll
            for (int mt = 0; mt < 2; mt++) {
                #pragma unroll
                for (int bp = 0; bp < 4; bp++) {
                    MMA_BF16(acc[mt][bp * 2 + 0], af[mt], bf[bp][0], bf[bp][1]);
                    MMA_BF16(acc[mt][bp * 2 + 1], af[mt], bf[bp][2], bf[bp][3]);
                }
            }
        }
    }
    __syncthreads();

    // stage C (+bias) to smem: Cf[px][e]
    float* Cf = (float*)smem;
    const float* sbias = (const float*)(smem + CV_SBIAS);
    #pragma unroll
    for (int mt = 0; mt < 2; mt++) {
        #pragma unroll
        for (int j = 0; j < 8; j++) {
            int row = warp_m * 32 + mt * 16 + (lane >> 2);
            int col = warp_n * 64 + j * 8 + 2 * (lane & 3);
            Cf[row * CV_CST + col]           = acc[mt][j][0] + sbias[col];
            Cf[row * CV_CST + col + 1]       = acc[mt][j][1] + sbias[col + 1];
            Cf[(row + 8) * CV_CST + col]     = acc[mt][j][2] + sbias[col];
            Cf[(row + 8) * CV_CST + col + 1] = acc[mt][j][3] + sbias[col + 1];
        }
    }
    __syncthreads();

    // norm over e
    const int px = tid & 127;
    const int q = tid >> 7;
    float* psum = (float*)(smem + CV_PSUM);
    {
        float s = 0.f;
        #pragma unroll 8
        for (int e = q * 64; e < q * 64 + 64; e++) {
            float v = Cf[px * CV_CST + e];
            s += v * v;
        }
        psum[q * 128 + px] = s;
    }
    __syncthreads();
    {
        float tot = psum[px] + psum[128 + px] + psum[256 + px] + psum[384 + px];
        float inv = 1.f / fmaxf(sqrtf(tot), 1e-12f);
        size_t rowb = (size_t)(p0 + px) * AK;
        // this thread owns e range [q*64, q*64+64): 8 groups of 8 bf16
        #pragma unroll
        for (int g = 0; g < 8; g++) {
            int e = q * 64 + g * 8;
            uint32_t ph[4], pl[4];
            #pragma unroll
            for (int j = 0; j < 4; j++) {
                float f0 = Cf[px * CV_CST + e + 2 * j]     * inv;
                float f1 = Cf[px * CV_CST + e + 2 * j + 1] * inv;
                __nv_bfloat16 h0 = __float2bfloat16(f0);
                __nv_bfloat16 h1 = __float2bfloat16(f1);
                ph[j] = pk_bf2(h0, h1);
                pl[j] = pk_bf2(__float2bfloat16(f0 - __bfloat162float(h0)),
                               __float2bfloat16(f1 - __bfloat162float(h1)));
            }
            *(uint4*)&g_embA[rowb + e]       = *(uint4*)ph;
            *(uint4*)&g_embA[rowb + 256 + e] = *(uint4*)pl;
        }
    }
}

// =====================================================================
// Kernel 3: main bf16 mma.sync GEMM (128px x 96col, K=768 via [hi|lo] A)
// =====================================================================
#define SMA(buf) ((buf) ? 16384 : 0)
#define SMB(buf) (32768 + ((buf) ? 12288 : 0))
#define CSTRIDE 129
#define SUMBUF_OFF 49536
#define SMEM_TOT 57344

__global__ __launch_bounds__(256) void dml_main_kernel(float* __restrict__ out)
{
    extern __shared__ char smem[];
    const uint32_t sbase = smem_u32(smem);
    const int tid = threadIdx.x;
    const int lane = tid & 31;
    const int wid = tid >> 5;
    const int warp_m = wid & 3;
    const int warp_n = wid >> 2;
    const int p0 = (int)blockIdx.x * MPX;
    const int rt = (int)blockIdx.y;
    const int r1 = rt * NT_R;
    const int bimg = p0 >> 12;
    const int hw0 = p0 & 4095;

    const __nv_bfloat16* abase = g_embA + (size_t)p0 * AK;
    const __nv_bfloat16* bbase = g_B + (size_t)rt * NCOLS * EK;

    float acc[2][6][4];
    #pragma unroll
    for (int mt = 0; mt < 2; mt++)
        #pragma unroll
        for (int j = 0; j < 6; j++)
            #pragma unroll
            for (int q = 0; q < 4; q++) acc[mt][j][q] = 0.f;

    uint4 va[4], vb[3];
    // prologue: chunk 0 (A offset 0)
    #pragma unroll
    for (int i = 0; i < 4; i++) {
        int idx = tid + 256 * i, row = idx >> 3, c = idx & 7;
        va[i] = *((const uint4*)(abase + (size_t)row * AK) + c);
    }
    #pragma unroll
    for (int i = 0; i < 3; i++) {
        int idx = tid + 256 * i, row = idx >> 3, c = idx & 7;
        vb[i] = *((const uint4*)(bbase + (size_t)row * EK) + c);
    }

    for (int s = 0; s < 12; s++) {
        const int buf = s & 1;
        char* sa = smem + SMA(buf);
        char* sb = smem + SMB(buf);
        #pragma unroll
        for (int i = 0; i < 4; i++) {
            int idx = tid + 256 * i, row = idx >> 3, c = idx & 7;
            *(uint4*)(sa + (((row << 3) + (c ^ (row & 7))) << 4)) = va[i];
        }
        #pragma unroll
        for (int i = 0; i < 3; i++) {
            int idx = tid + 256 * i, row = idx >> 3, c = idx & 7;
            *(uint4*)(sb + (((row << 3) + (c ^ (row & 7))) << 4)) = vb[i];
        }
        __syncthreads();

        if (s < 11) {
            const int sn = s + 1;
            const int k0b = sn * 64;
            const int k0a = ((sn & 3) << 6) + (((sn >> 2) == 1) ? 256 : 0);
            #pragma unroll
            for (int i = 0; i < 4; i++) {
                int idx = tid + 256 * i, row = idx >> 3, c = idx & 7;
                va[i] = *((const uint4*)(abase + (size_t)row * AK + k0a) + c);
            }
            #pragma unroll
            for (int i = 0; i < 3; i++) {
                int idx = tid + 256 * i, row = idx >> 3, c = idx & 7;
                vb[i] = *((const uint4*)(bbase + (size_t)row * EK + k0b) + c);
            }
        }

        const uint32_t saA = sbase + SMA(buf);
        const uint32_t saB = sbase + SMB(buf);
        #pragma unroll
        for (int kk = 0; kk < 4; kk++) {
            uint32_t af[2][4];
            #pragma unroll
            for (int mt = 0; mt < 2; mt++) {
                int row = warp_m * 32 + mt * 16 + (lane & 15);
                int c = kk * 2 + (lane >> 4);
                uint32_t addr = saA + (((row << 3) + (c ^ (row & 7))) << 4);
                LDSM_X4(af[mt][0], af[mt][1], af[mt][2], af[mt][3], addr);
            }
            uint32_t bf[3][4];
            #pragma unroll
            for (int bp = 0; bp < 3; bp++) {
                int row = warp_n * 48 + bp * 16 + ((lane >> 4) << 3) + (lane & 7);
                int c = kk * 2 + ((lane >> 3) & 1);
                uint32_t addr = saB + (((row << 3) + (c ^ (row & 7))) << 4);
                LDSM_X4(bf[bp][0], bf[bp][1], bf[bp][2], bf[bp][3], addr);
            }
            #pragma unroll
            for (int mt = 0; mt < 2; mt++) {
                #pragma unroll
                for (int bp = 0; bp < 3; bp++) {
                    MMA_BF16(acc[mt][bp * 2 + 0], af[mt], bf[bp][0], bf[bp][1]);
                    MMA_BF16(acc[mt][bp * 2 + 1], af[mt], bf[bp][2], bf[bp][3]);
                }
            }
        }
        __syncthreads();
    }

    // stage C to smem
    float* Cf = (float*)smem;
    #pragma unroll
    for (int mt = 0; mt < 2; mt++) {
        #pragma unroll
        for (int j = 0; j < 6; j++) {
            int row = warp_m * 32 + mt * 16 + (lane >> 2);
            int col = warp_n * 48 + j * 8 + 2 * (lane & 3);
            Cf[col * CSTRIDE + row]           = acc[mt][j][0];
            Cf[(col + 1) * CSTRIDE + row]     = acc[mt][j][1];
            Cf[col * CSTRIDE + row + 8]       = acc[mt][j][2];
            Cf[(col + 1) * CSTRIDE + row + 8] = acc[mt][j][3];
        }
    }
    __syncthreads();

    // epilogue
    const int px = tid & 127;
    const int rg = tid >> 7;
    const int hw = hw0 + px;
    const size_t oimg = (size_t)bimg * RNUM;
    float ssum = 0.f;

    #pragma unroll
    for (int pass = 0; pass < 16; pass++) {
        int rloc = pass * 2 + rg;
        int r = r1 + rloc;
        if (r < RNUM) {
            float dp = Cf[rloc * CSTRIDE + px];
            float d0 = Cf[(32 + rloc) * CSTRIDE + px];
            float d1 = Cf[(64 + rloc) * CSTRIDE + px];
            float dp2 = fmaxf(2.f - 2.f * dp, 0.f);
            float d02 = fmaxf(2.f - 2.f * d0, 0.f);
            float d12 = fmaxf(2.f - 2.f * d1, 0.f);
            float dmin2 = fminf(d02, d12);
            float dpl = dp2 * rsqrtf(fmaxf(dp2, 1e-30f));
            float d0l = d02 * rsqrtf(fmaxf(d02, 1e-30f));
            float d1l = d12 * rsqrtf(fmaxf(d12, 1e-30f));
            float dminl = fminf(d0l, d1l);
            float fcn = __expf(-2.f * dmin2);
            float fpo = __expf(-2.f * dp2);
            float tt = dpl + 0.3f * (2.f - dminl);
            float fpr = __expf(-2.f * tt * tt);

            size_t base = (oimg + r) * HWSZ + hw;
            out[OFF_DIST + base]   = dpl;
            out[OFF_CLS + base]    = fpr;
            out[OFF_CLSNEG + base] = fcn;
            out[OFF_PORI + base]   = fpo;
            size_t bn = (oimg + r) * 2 * HWSZ + hw;
            out[OFF_DNEG + bn]        = d0l;
            out[OFF_DNEG + bn + HWSZ] = d1l;
            ssum += fpr;
        }
    }

    __syncthreads();
    float* sumbuf = (float*)(smem + SUMBUF_OFF);
    sumbuf[tid] = ssum;
    __syncthreads();
    if (tid < 128)
        g_part[rt][p0 + tid] = sumbuf[tid] + sumbuf[tid + 128];
}

// =====================================================================
// Kernel 4: combine partials -> 1/sum
// =====================================================================
__global__ __launch_bounds__(256) void inv_sum_kernel()
{
    int i = blockIdx.x * 256 + threadIdx.x;
    float s = 0.f;
    #pragma unroll
    for (int t = 0; t < NTILES; t++) s += g_part[t][i];
    g_sum[i] = 1.f / s;
}

// =====================================================================
// Kernel 5: cls_score *= 1/sum
// =====================================================================
__global__ __launch_bounds__(256) void scale_cls_kernel(float* __restrict__ out)
{
    int row = blockIdx.y;
    int b = row / RNUM;
    int hw = blockIdx.x * 1024 + threadIdx.x * 4;
    float4 s = *(float4*)&g_sum[b * 4096 + hw];
    float4 v = *(float4*)&out[OFF_CLS + (size_t)row * HWSZ + hw];
    v.x *= s.x; v.y *= s.y; v.z *= s.z; v.w *= s.w;
    *(float4*)&out[OFF_CLS + (size_t)row * HWSZ + hw] = v;
}

// =====================================================================
extern "C" void kernel_launch(void* const* d_in, const int* in_sizes, int n_in,
                              void* d_out, int out_size)
{
    (void)in_sizes; (void)n_in; (void)out_size;
    const float* x      = (const float*)d_in[0];
    const float* conv_w = (const float*)d_in[1];
    const float* conv_b = (const float*)d_in[2];
    const float* reps   = (const float*)d_in[3];
    const float* neg_w  = (const float*)d_in[4];
    const float* neg_b  = (const float*)d_in[5];
    float* out = (float*)d_out;

    cudaFuncSetAttribute(dml_main_kernel,
                         cudaFuncAttributeMaxDynamicSharedMemorySize, SMEM_TOT);
    cudaFuncSetAttribute(conv_mma_kernel,
                         cudaFuncAttributeMaxDynamicSharedMemorySize, CV_SMEM);

    transpose_kernel<<<dim3(128, 8, 16), 256>>>(x);
    prep_reps_kernel<<<48, 256>>>(reps, neg_w, neg_b);
    conv_mma_kernel<<<512, 512, CV_SMEM>>>(conv_w, conv_b);
    dml_main_kernel<<<dim3(512, NTILES), 256, SMEM_TOT>>>(out);
    inv_sum_kernel<<<256, 256>>>();
    scale_cls_kernel<<<dim3(4, BATCH * RNUM), 256>>>(out);
}

// round 7
// speedup vs baseline: 1.2402x; 1.2402x over previous
#include <cuda_runtime.h>
#include <cuda_fp16.h>
#include <cstdint>
#include <math.h>

// ---------------- problem constants ----------------
#define BATCH 16
#define EDIM  256
#define HWSZ  4096
#define NPIX  65536
#define RNUM  365
#define KSEG  512            // fp16 split-2: A'=[hi|lo], B'=[hi|hi]
#define NT_R  32
#define NCOLS 96             // 3 modes * 32 r
#define NTILES 12
#define MPX   128
#define NCHUNK 8             // 512 / 64

#define TOT1     ((size_t)BATCH * RNUM * HWSZ)
#define OFF_CLS    ((size_t)0)
#define OFF_CLSNEG (TOT1)
#define OFF_DIST   (2*TOT1)
#define OFF_DNEG   (3*TOT1)
#define OFF_PORI   (5*TOT1)

// ---------------- static device scratch ----------------
__device__ float g_xt[(size_t)NPIX * EDIM];                // 64 MB  x transposed [px][c]
__device__ __half g_embA[(size_t)NPIX * KSEG];             // 64 MB  emb split [hi|lo]
__device__ __half g_B[(size_t)NTILES * NCOLS * KSEG];      // 1.2 MB reps [hi|hi]
__device__ float g_part[NTILES][NPIX];
__device__ float g_sum[NPIX];

// ---------------- helpers ----------------
__device__ __forceinline__ uint32_t pk_hf2(__half a, __half b) {
    unsigned short ua = __half_as_ushort(a), ub = __half_as_ushort(b);
    return (uint32_t)ua | ((uint32_t)ub << 16);
}
__device__ __forceinline__ uint32_t smem_u32(const void* p) {
    uint32_t a;
    asm("{ .reg .u64 t; cvta.to.shared.u64 t, %1; cvt.u32.u64 %0, t; }" : "=r"(a) : "l"(p));
    return a;
}
__device__ __forceinline__ uint2 cvt_f4h(float4 v, bool lo) {
    __half h0 = __float2half(v.x), h1 = __float2half(v.y),
           h2 = __float2half(v.z), h3 = __float2half(v.w);
    if (lo) {
        h0 = __float2half(v.x - __half2float(h0));
        h1 = __float2half(v.y - __half2float(h1));
        h2 = __float2half(v.z - __half2float(h2));
        h3 = __float2half(v.w - __half2float(h3));
    }
    uint2 r; r.x = pk_hf2(h0, h1); r.y = pk_hf2(h2, h3); return r;
}

#define LDSM_X4(r0, r1, r2, r3, addr)                                          \
    asm volatile("ldmatrix.sync.aligned.m8n8.x4.shared.b16 {%0,%1,%2,%3}, [%4];" \
        : "=r"(r0), "=r"(r1), "=r"(r2), "=r"(r3) : "r"(addr))

#define MMA_F16(c, a, b0, b1)                                                  \
    asm volatile("mma.sync.aligned.m16n8k16.row.col.f32.f16.f16.f32 "          \
        "{%0,%1,%2,%3}, {%4,%5,%6,%7}, {%8,%9}, {%0,%1,%2,%3};"                \
        : "+f"((c)[0]), "+f"((c)[1]), "+f"((c)[2]), "+f"((c)[3])               \
        : "r"((a)[0]), "r"((a)[1]), "r"((a)[2]), "r"((a)[3]), "r"(b0), "r"(b1))

// =====================================================================
// Kernel 0: transpose x[b][c][hw] -> g_xt[b*4096+hw][c]
// =====================================================================
__global__ __launch_bounds__(256) void transpose_kernel(const float* __restrict__ x)
{
    __shared__ float tl[32][33];
    const int hw0 = blockIdx.x * 32, c0 = blockIdx.y * 32, b = blockIdx.z;
    const int tx = threadIdx.x & 31, ty = threadIdx.x >> 5;
    const float* src = x + ((size_t)b * 256 + c0) * 4096 + hw0;
    #pragma unroll
    for (int j = 0; j < 4; j++)
        tl[ty * 4 + j][tx] = src[(size_t)(ty * 4 + j) * 4096 + tx];
    __syncthreads();
    float* dst = g_xt + ((size_t)b * 4096 + hw0) * 256 + c0;
    #pragma unroll
    for (int j = 0; j < 4; j++)
        dst[(size_t)(ty * 4 + j) * 256 + tx] = tl[tx][ty * 4 + j];
}

// =====================================================================
// Kernel 1: build B' (pos / neg0 / neg1, normalized, fp16 [hi|hi]).
// =====================================================================
__global__ __launch_bounds__(256) void prep_reps_kernel(
    const float* __restrict__ reps,
    const float* __restrict__ negw,
    const float* __restrict__ negb)
{
    __shared__ float s_rep[8][256];
    __shared__ float s_off[8][512];
    const int tid = threadIdx.x;
    const int r0 = blockIdx.x * 8;
    const int w = tid >> 5, lane = tid & 31;

    #pragma unroll
    for (int i = 0; i < 8; i++) {
        int r = r0 + i;
        s_rep[i][tid] = (r < RNUM) ? reps[r * 256 + tid] : 0.f;
    }
    __syncthreads();

    for (int jj = 0; jj < 64; jj++) {
        int j = w * 64 + jj;
        float part[8];
        #pragma unroll
        for (int rl = 0; rl < 8; rl++) part[rl] = 0.f;
        #pragma unroll
        for (int i2 = 0; i2 < 8; i2++) {
            int k = lane + 32 * i2;
            float wv = negw[j * 256 + k];
            #pragma unroll
            for (int rl = 0; rl < 8; rl++) part[rl] += wv * fabsf(s_rep[rl][k]);
        }
        #pragma unroll
        for (int off = 16; off > 0; off >>= 1) {
            #pragma unroll
            for (int rl = 0; rl < 8; rl++)
                part[rl] += __shfl_xor_sync(0xffffffffu, part[rl], off);
        }
        if (lane < 8) s_off[lane][j] = part[lane] + negb[j];
    }
    __syncthreads();

    #pragma unroll
    for (int pi = 0; pi < 2; pi++) {
        int pair = w + pi * 8;
        int i = pair & 7, m = pair >> 3;
        float vals[8];
        float ss = 0.f;
        #pragma unroll
        for (int q = 0; q < 8; q++) {
            int e = lane + 32 * q;
            float rv = s_rep[i][e];
            float sg = (rv > 0.f ? 1.f : 0.f) - (rv < 0.f ? 1.f : 0.f);
            float v = (s_off[i][m * 256 + e] + fabsf(rv)) * sg;
            vals[q] = v;
            ss += v * v;
        }
        #pragma unroll
        for (int off = 16; off > 0; off >>= 1) ss += __shfl_xor_sync(0xffffffffu, ss, off);
        float inv = 1.f / fmaxf(sqrtf(ss), 1e-12f);
        int r = r0 + i;
        int t = r >> 5, rl = r & 31;
        size_t rowb = ((size_t)(t * NCOLS + (1 + m) * 32 + rl)) * KSEG;
        #pragma unroll
        for (int q = 0; q < 8; q++) {
            int e = lane + 32 * q;
            __half hb = __float2half(vals[q] * inv);
            g_B[rowb + e]       = hb;
            g_B[rowb + 256 + e] = hb;
        }
    }
    #pragma unroll
    for (int i = 0; i < 8; i++) {
        int r = r0 + i;
        int t = r >> 5, rl = r & 31;
        __half hb = __float2half(s_rep[i][tid]);
        size_t rowb = ((size_t)(t * NCOLS + rl)) * KSEG + tid;
        g_B[rowb]       = hb;
        g_B[rowb + 256] = hb;
    }
}

// =====================================================================
// Kernel 2: conv via mma.sync fp16 split-2. C[px(128)][e(256)], K=512.
// 512 threads, 16 warps (4m x 4n). Single-buffered smem.
// =====================================================================
#define CV_SA 0
#define CV_SB 16384
#define CV_CST 257
#define CV_PSUM (131584)
#define CV_SBIAS (131584 + 2048)
#define CV_SMEM (131584 + 2048 + 1024)     // 134656

__global__ __launch_bounds__(512) void conv_mma_kernel(
    const float* __restrict__ W,
    const float* __restrict__ bias)
{
    extern __shared__ char smem[];
    const uint32_t sbase = smem_u32(smem);
    const int tid = threadIdx.x;
    const int lane = tid & 31;
    const int wid = tid >> 5;
    const int warp_m = wid & 3;
    const int warp_n = wid >> 2;
    const int p0 = blockIdx.x * MPX;

    if (tid < 256) ((float*)(smem + CV_SBIAS))[tid] = bias[tid];

    float acc[2][8][4];
    #pragma unroll
    for (int mt = 0; mt < 2; mt++)
        #pragma unroll
        for (int j = 0; j < 8; j++)
            #pragma unroll
            for (int q = 0; q < 4; q++) acc[mt][j][q] = 0.f;

    for (int s = 0; s < NCHUNK; s++) {
        const int c0 = (s & 3) << 6;
        const bool aLo = (s >= 4);
        __syncthreads();
        // A: xt rows p0..p0+127, cols c0..c0+63 (fp32 -> fp16 hi/lo)
        #pragma unroll
        for (int i = 0; i < 4; i++) {
            int idx = tid + 512 * i;
            int row = idx >> 4, c4 = idx & 15;
            float4 v = *(const float4*)&g_xt[(size_t)(p0 + row) * 256 + c0 + c4 * 4];
            uint2 u = cvt_f4h(v, aLo);
            int g = c4 >> 1, half = c4 & 1;
            *(uint2*)(smem + CV_SA + (row << 7) + (((g ^ (row & 7))) << 4) + (half << 3)) = u;
        }
        // B: W rows e 0..255, cols c0..c0+63 (always hi)
        #pragma unroll
        for (int i = 0; i < 8; i++) {
            int idx = tid + 512 * i;
            int row = idx >> 4, c4 = idx & 15;
            float4 v = *(const float4*)&W[(size_t)row * 256 + c0 + c4 * 4];
            uint2 u = cvt_f4h(v, false);
            int g = c4 >> 1, half = c4 & 1;
            *(uint2*)(smem + CV_SB + (row << 7) + (((g ^ (row & 7))) << 4) + (half << 3)) = u;
        }
        __syncthreads();

        const uint32_t saA = sbase + CV_SA;
        const uint32_t saB = sbase + CV_SB;
        #pragma unroll
        for (int kk = 0; kk < 4; kk++) {
            uint32_t af[2][4];
            #pragma unroll
            for (int mt = 0; mt < 2; mt++) {
                int row = warp_m * 32 + mt * 16 + (lane & 15);
                int c = kk * 2 + (lane >> 4);
                uint32_t addr = saA + (((row << 3) + (c ^ (row & 7))) << 4);
                LDSM_X4(af[mt][0], af[mt][1], af[mt][2], af[mt][3], addr);
            }
            uint32_t bf[4][4];
            #pragma unroll
            for (int bp = 0; bp < 4; bp++) {
                int row = warp_n * 64 + bp * 16 + ((lane >> 4) << 3) + (lane & 7);
                int c = kk * 2 + ((lane >> 3) & 1);
                uint32_t addr = saB + (((row << 3) + (c ^ (row & 7))) << 4);
                LDSM_X4(bf[bp][0], bf[bp][1], bf[bp][2], bf[bp][3], addr);
            }
            #pragma unroll
            for (int mt = 0; mt < 2; mt++) {
                #pragma unroll
                for (int bp = 0; bp < 4; bp++) {
                    MMA_F16(acc[mt][bp * 2 + 0], af[mt], bf[bp][0], bf[bp][1]);
                    MMA_F16(acc[mt][bp * 2 + 1], af[mt], bf[bp][2], bf[bp][3]);
                }
            }
        }
    }
    __syncthreads();

    // stage C (+bias) to smem: Cf[px][e]
    float* Cf = (float*)smem;
    const float* sbias = (const float*)(smem + CV_SBIAS);
    #pragma unroll
    for (int mt = 0; mt < 2; mt++) {
        #pragma unroll
        for (int j = 0; j < 8; j++) {
            int row = warp_m * 32 + mt * 16 + (lane >> 2);
            int col = warp_n * 64 + j * 8 + 2 * (lane & 3);
            Cf[row * CV_CST + col]           = acc[mt][j][0] + sbias[col];
            Cf[row * CV_CST + col + 1]       = acc[mt][j][1] + sbias[col + 1];
            Cf[(row + 8) * CV_CST + col]     = acc[mt][j][2] + sbias[col];
            Cf[(row + 8) * CV_CST + col + 1] = acc[mt][j][3] + sbias[col + 1];
        }
    }
    __syncthreads();

    // norm over e
    const int px = tid & 127;
    const int q = tid >> 7;
    float* psum = (float*)(smem + CV_PSUM);
    {
        float s = 0.f;
        #pragma unroll 8
        for (int e = q * 64; e < q * 64 + 64; e++) {
            float v = Cf[px * CV_CST + e];
            s += v * v;
        }
        psum[q * 128 + px] = s;
    }
    __syncthreads();
    {
        float tot = psum[px] + psum[128 + px] + psum[256 + px] + psum[384 + px];
        float inv = 1.f / fmaxf(sqrtf(tot), 1e-12f);
        size_t rowb = (size_t)(p0 + px) * KSEG;
        #pragma unroll
        for (int g = 0; g < 8; g++) {
            int e = q * 64 + g * 8;
            uint32_t ph[4], pl[4];
            #pragma unroll
            for (int j = 0; j < 4; j++) {
                float f0 = Cf[px * CV_CST + e + 2 * j]     * inv;
                float f1 = Cf[px * CV_CST + e + 2 * j + 1] * inv;
                __half h0 = __float2half(f0);
                __half h1 = __float2half(f1);
                ph[j] = pk_hf2(h0, h1);
                pl[j] = pk_hf2(__float2half(f0 - __half2float(h0)),
                               __float2half(f1 - __half2float(h1)));
            }
            *(uint4*)&g_embA[rowb + e]       = *(uint4*)ph;
            *(uint4*)&g_embA[rowb + 256 + e] = *(uint4*)pl;
        }
    }
}

// =====================================================================
// Kernel 3: main fp16 mma.sync GEMM (128px x 96col, K=512) + epilogue.
// =====================================================================
#define SMA(buf) ((buf) ? 16384 : 0)
#define SMB(buf) (32768 + ((buf) ? 12288 : 0))
#define CSTRIDE 129
#define SUMBUF_OFF 49536
#define SMEM_TOT 57344

__global__ __launch_bounds__(256) void dml_main_kernel(float* __restrict__ out)
{
    extern __shared__ char smem[];
    const uint32_t sbase = smem_u32(smem);
    const int tid = threadIdx.x;
    const int lane = tid & 31;
    const int wid = tid >> 5;
    const int warp_m = wid & 3;
    const int warp_n = wid >> 2;
    const int p0 = (int)blockIdx.x * MPX;
    const int rt = (int)blockIdx.y;
    const int r1 = rt * NT_R;
    const int bimg = p0 >> 12;
    const int hw0 = p0 & 4095;

    const __half* abase = g_embA + (size_t)p0 * KSEG;
    const __half* bbase = g_B + (size_t)rt * NCOLS * KSEG;

    float acc[2][6][4];
    #pragma unroll
    for (int mt = 0; mt < 2; mt++)
        #pragma unroll
        for (int j = 0; j < 6; j++)
            #pragma unroll
            for (int q = 0; q < 4; q++) acc[mt][j][q] = 0.f;

    uint4 va[4], vb[3];
    #pragma unroll
    for (int i = 0; i < 4; i++) {
        int idx = tid + 256 * i, row = idx >> 3, c = idx & 7;
        va[i] = *((const uint4*)(abase + (size_t)row * KSEG) + c);
    }
    #pragma unroll
    for (int i = 0; i < 3; i++) {
        int idx = tid + 256 * i, row = idx >> 3, c = idx & 7;
        vb[i] = *((const uint4*)(bbase + (size_t)row * KSEG) + c);
    }

    for (int s = 0; s < NCHUNK; s++) {
        const int buf = s & 1;
        char* sa = smem + SMA(buf);
        char* sb = smem + SMB(buf);
        #pragma unroll
        for (int i = 0; i < 4; i++) {
            int idx = tid + 256 * i, row = idx >> 3, c = idx & 7;
            *(uint4*)(sa + (((row << 3) + (c ^ (row & 7))) << 4)) = va[i];
        }
        #pragma unroll
        for (int i = 0; i < 3; i++) {
            int idx = tid + 256 * i, row = idx >> 3, c = idx & 7;
            *(uint4*)(sb + (((row << 3) + (c ^ (row & 7))) << 4)) = vb[i];
        }
        __syncthreads();

        if (s < NCHUNK - 1) {
            const int k0 = (s + 1) * 64;
            #pragma unroll
            for (int i = 0; i < 4; i++) {
                int idx = tid + 256 * i, row = idx >> 3, c = idx & 7;
                va[i] = *((const uint4*)(abase + (size_t)row * KSEG + k0) + c);
            }
            #pragma unroll
            for (int i = 0; i < 3; i++) {
                int idx = tid + 256 * i, row = idx >> 3, c = idx & 7;
                vb[i] = *((const uint4*)(bbase + (size_t)row * KSEG + k0) + c);
            }
        }

        const uint32_t saA = sbase + SMA(buf);
        const uint32_t saB = sbase + SMB(buf);
        #pragma unroll
        for (int kk = 0; kk < 4; kk++) {
            uint32_t af[2][4];
            #pragma unroll
            for (int mt = 0; mt < 2; mt++) {
                int row = warp_m * 32 + mt * 16 + (lane & 15);
                int c = kk * 2 + (lane >> 4);
                uint32_t addr = saA + (((row << 3) + (c ^ (row & 7))) << 4);
                LDSM_X4(af[mt][0], af[mt][1], af[mt][2], af[mt][3], addr);
            }
            uint32_t bf[3][4];
            #pragma unroll
            for (int bp = 0; bp < 3; bp++) {
                int row = warp_n * 48 + bp * 16 + ((lane >> 4) << 3) + (lane & 7);
                int c = kk * 2 + ((lane >> 3) & 1);
                uint32_t addr = saB + (((row << 3) + (c ^ (row & 7))) << 4);
                LDSM_X4(bf[bp][0], bf[bp][1], bf[bp][2], bf[bp][3], addr);
            }
            #pragma unroll
            for (int mt = 0; mt < 2; mt++) {
                #pragma unroll
                for (int bp = 0; bp < 3; bp++) {
                    MMA_F16(acc[mt][bp * 2 + 0], af[mt], bf[bp][0], bf[bp][1]);
                    MMA_F16(acc[mt][bp * 2 + 1], af[mt], bf[bp][2], bf[bp][3]);
                }
            }
        }
        __syncthreads();
    }

    // stage C to smem
    float* Cf = (float*)smem;
    #pragma unroll
    for (int mt = 0; mt < 2; mt++) {
        #pragma unroll
        for (int j = 0; j < 6; j++) {
            int row = warp_m * 32 + mt * 16 + (lane >> 2);
            int col = warp_n * 48 + j * 8 + 2 * (lane & 3);
            Cf[col * CSTRIDE + row]           = acc[mt][j][0];
            Cf[(col + 1) * CSTRIDE + row]     = acc[mt][j][1];
            Cf[col * CSTRIDE + row + 8]       = acc[mt][j][2];
            Cf[(col + 1) * CSTRIDE + row + 8] = acc[mt][j][3];
        }
    }
    __syncthreads();

    // epilogue
    const int px = tid & 127;
    const int rg = tid >> 7;
    const int hw = hw0 + px;
    const size_t oimg = (size_t)bimg * RNUM;
    float ssum = 0.f;

    #pragma unroll
    for (int pass = 0; pass < 16; pass++) {
        int rloc = pass * 2 + rg;
        int r = r1 + rloc;
        if (r < RNUM) {
            float dp = Cf[rloc * CSTRIDE + px];
            float d0 = Cf[(32 + rloc) * CSTRIDE + px];
            float d1 = Cf[(64 + rloc) * CSTRIDE + px];
            float dp2 = fmaxf(2.f - 2.f * dp, 0.f);
            float d02 = fmaxf(2.f - 2.f * d0, 0.f);
            float d12 = fmaxf(2.f - 2.f * d1, 0.f);
            float dmin2 = fminf(d02, d12);
            float dpl = dp2 * rsqrtf(fmaxf(dp2, 1e-30f));
            float d0l = d02 * rsqrtf(fmaxf(d02, 1e-30f));
            float d1l = d12 * rsqrtf(fmaxf(d12, 1e-30f));
            float dminl = fminf(d0l, d1l);
            float fcn = __expf(-2.f * dmin2);
            float fpo = __expf(-2.f * dp2);
            float tt = dpl + 0.3f * (2.f - dminl);
            float fpr = __expf(-2.f * tt * tt);

            size_t base = (oimg + r) * HWSZ + hw;
            out[OFF_DIST + base]   = dpl;
            out[OFF_CLS + base]    = fpr;
            out[OFF_CLSNEG + base] = fcn;
            out[OFF_PORI + base]   = fpo;
            size_t bn = (oimg + r) * 2 * HWSZ + hw;
            out[OFF_DNEG + bn]        = d0l;
            out[OFF_DNEG + bn + HWSZ] = d1l;
            ssum += fpr;
        }
    }

    __syncthreads();
    float* sumbuf = (float*)(smem + SUMBUF_OFF);
    sumbuf[tid] = ssum;
    __syncthreads();
    if (tid < 128)
        g_part[rt][p0 + tid] = sumbuf[tid] + sumbuf[tid + 128];
}

// =====================================================================
// Kernel 4: combine partials -> 1/sum
// =====================================================================
__global__ __launch_bounds__(256) void inv_sum_kernel()
{
    int i = blockIdx.x * 256 + threadIdx.x;
    float s = 0.f;
    #pragma unroll
    for (int t = 0; t < NTILES; t++) s += g_part[t][i];
    g_sum[i] = 1.f / s;
}

// =====================================================================
// Kernel 5: cls_score *= 1/sum
// =====================================================================
__global__ __launch_bounds__(256) void scale_cls_kernel(float* __restrict__ out)
{
    int row = blockIdx.y;
    int b = row / RNUM;
    int hw = blockIdx.x * 1024 + threadIdx.x * 4;
    float4 s = *(float4*)&g_sum[b * 4096 + hw];
    float4 v = *(float4*)&out[OFF_CLS + (size_t)row * HWSZ + hw];
    v.x *= s.x; v.y *= s.y; v.z *= s.z; v.w *= s.w;
    *(float4*)&out[OFF_CLS + (size_t)row * HWSZ + hw] = v;
}

// =====================================================================
extern "C" void kernel_launch(void* const* d_in, const int* in_sizes, int n_in,
                              void* d_out, int out_size)
{
    (void)in_sizes; (void)n_in; (void)out_size;
    const float* x      = (const float*)d_in[0];
    const float* conv_w = (const float*)d_in[1];
    const float* conv_b = (const float*)d_in[2];
    const float* reps   = (const float*)d_in[3];
    const float* neg_w  = (const float*)d_in[4];
    const float* neg_b  = (const float*)d_in[5];
    float* out = (float*)d_out;

    cudaFuncSetAttribute(dml_main_kernel,
                         cudaFuncAttributeMaxDynamicSharedMemorySize, SMEM_TOT);
    cudaFuncSetAttribute(conv_mma_kernel,
                         cudaFuncAttributeMaxDynamicSharedMemorySize, CV_SMEM);

    transpose_kernel<<<dim3(128, 8, 16), 256>>>(x);
    prep_reps_kernel<<<48, 256>>>(reps, neg_w, neg_b);
    conv_mma_kernel<<<512, 512, CV_SMEM>>>(conv_w, conv_b);
    dml_main_kernel<<<dim3(512, NTILES), 256, SMEM_TOT>>>(out);
    inv_sum_kernel<<<256, 256>>>();
    scale_cls_kernel<<<dim3(4, BATCH * RNUM), 256>>>(out);
}